// round 15
// baseline (speedup 1.0000x reference)
#include <cuda_runtime.h>
#include <cuda_bf16.h>
#include <cstdint>

#define N_NODES 50000
#define N_EDGES 800000
#define D_IN 128
#define N_HEADS 8
#define PER_HEAD 16
#define LEAKY_ALPHA 0.2f

// ---------------- static device scratch (no allocations allowed) ------------
__device__ float g_q[(size_t)N_NODES * 128];         // 25.6 MB
__device__ float g_k[(size_t)N_NODES * 128];         // 25.6 MB
__device__ int   g_count[N_NODES];                   // in-degree histogram
__device__ int   g_offset[N_NODES + 1];              // CSR row offsets
__device__ int   g_cursor[N_NODES];                  // scatter cursors
__device__ int   g_src_sorted[N_EDGES];              // src node per CSR slot

__device__ __forceinline__ float lrelu(float v) {
    return v > 0.0f ? v : LEAKY_ALPHA * v;
}

__device__ __forceinline__ uint32_t f2tf32(float f) {
    uint32_t r;
    asm("cvt.rna.tf32.f32 %0, %1;" : "=r"(r) : "f"(f));
    return r;
}

__device__ __forceinline__ void mma_tf32(float c[4],
                                         uint32_t a0, uint32_t a1, uint32_t a2, uint32_t a3,
                                         uint32_t b0, uint32_t b1) {
    asm volatile(
        "mma.sync.aligned.m16n8k8.row.col.f32.tf32.tf32.f32 "
        "{%0,%1,%2,%3}, {%4,%5,%6,%7}, {%8,%9}, {%0,%1,%2,%3};"
        : "+f"(c[0]), "+f"(c[1]), "+f"(c[2]), "+f"(c[3])
        : "r"(a0), "r"(a1), "r"(a2), "r"(a3), "r"(b0), "r"(b1));
}

// ---------------- Kernel 1: Q/K GEMM on tensor cores (R13 config, 47.3us) ----
#define GEMM_BLOCK 256
#define GEMM_TILE_N 64
#define WS_STRIDE 136
#define XS_STRIDE 132
#define N_NODE_TILES ((N_NODES + GEMM_TILE_N - 1) / GEMM_TILE_N)  // 782

__global__ void __launch_bounds__(GEMM_BLOCK, 2)
qk_gemm_tc_kernel(const float* __restrict__ x,
                  const float* __restrict__ wq, const float* __restrict__ bq,
                  const float* __restrict__ wk, const float* __restrict__ bk) {
    extern __shared__ uint32_t smem_u[];
    uint32_t* ws = smem_u;                        // [128][136] = 17408 words
    uint32_t* xs = smem_u + 128 * WS_STRIDE;      // [64][132]  = 8448 words
    float* bs = (float*)(xs + GEMM_TILE_N * XS_STRIDE);  // 128 floats

    const int t = threadIdx.x;
    const bool is_q = (blockIdx.y == 0);
    const float* wsrc = is_q ? wq : wk;
    const float* bsrc = is_q ? bq : bk;
    float* gout = is_q ? g_q : g_k;

    for (int i = t; i < 128 * 128; i += GEMM_BLOCK) {
        int k = i >> 7, c = i & 127;
        ws[k * WS_STRIDE + c] = f2tf32(wsrc[i]);
    }
    if (t < 128) bs[t] = bsrc[t];

    const int warp = t >> 5;
    const int lane = t & 31;
    const int g = lane >> 2;
    const int tid4 = lane & 3;
    const int mb = (warp & 3) * 16;
    const int nb = (warp >> 2) * 64;

    for (int tile = blockIdx.x; tile < N_NODE_TILES; tile += gridDim.x) {
        const int n0 = tile * GEMM_TILE_N;
        __syncthreads();
        for (int i = t; i < GEMM_TILE_N * 32; i += GEMM_BLOCK) {
            int n = i >> 5, c4 = i & 31;
            int gn = n0 + n;
            float4 v = make_float4(0.f, 0.f, 0.f, 0.f);
            if (gn < N_NODES) v = *(const float4*)(x + (size_t)gn * 128 + c4 * 4);
            uint4 u;
            u.x = f2tf32(v.x); u.y = f2tf32(v.y);
            u.z = f2tf32(v.z); u.w = f2tf32(v.w);
            *(uint4*)(xs + n * XS_STRIDE + c4 * 4) = u;
        }
        __syncthreads();

        float acc[8][4];
#pragma unroll
        for (int nt = 0; nt < 8; nt++)
#pragma unroll
            for (int c = 0; c < 4; c++) acc[nt][c] = 0.f;

#pragma unroll 4
        for (int k0 = 0; k0 < 128; k0 += 8) {
            const uint32_t a0 = xs[(mb + g) * XS_STRIDE + k0 + tid4];
            const uint32_t a1 = xs[(mb + g + 8) * XS_STRIDE + k0 + tid4];
            const uint32_t a2 = xs[(mb + g) * XS_STRIDE + k0 + tid4 + 4];
            const uint32_t a3 = xs[(mb + g + 8) * XS_STRIDE + k0 + tid4 + 4];
#pragma unroll
            for (int nt = 0; nt < 8; nt++) {
                const uint32_t b0 = ws[(k0 + tid4) * WS_STRIDE + nb + nt * 8 + g];
                const uint32_t b1 = ws[(k0 + tid4 + 4) * WS_STRIDE + nb + nt * 8 + g];
                mma_tf32(acc[nt], a0, a1, a2, a3, b0, b1);
            }
        }

        const int r0 = n0 + mb + g;
        const int r1 = r0 + 8;
#pragma unroll
        for (int nt = 0; nt < 8; nt++) {
            const int col = nb + nt * 8 + tid4 * 2;
            const float b0v = bs[col];
            const float b1v = bs[col + 1];
            if (r0 < N_NODES) {
                float2 v = make_float2(acc[nt][0] + b0v, acc[nt][1] + b1v);
                *(float2*)(gout + (size_t)r0 * 128 + col) = v;
            }
            if (r1 < N_NODES) {
                float2 v = make_float2(acc[nt][2] + b0v, acc[nt][3] + b1v);
                *(float2*)(gout + (size_t)r1 * 128 + col) = v;
            }
        }
    }
}

// ---------------- CSR build: histogram -> scan -> scatter --------------------
__global__ void hist_kernel(const int* __restrict__ etgt) {
    int i = blockIdx.x * blockDim.x + threadIdx.x;
    if (i < N_EDGES) atomicAdd(&g_count[etgt[i]], 1);
}

#define SCAN_THREADS 1024
__global__ void scan_kernel() {
    __shared__ int partial[SCAN_THREADS];
    const int t = threadIdx.x;
    const int CHUNK = (N_NODES + SCAN_THREADS - 1) / SCAN_THREADS;  // 49
    const int base = t * CHUNK;

    int s = 0;
    for (int i = 0; i < CHUNK; i++) {
        int idx = base + i;
        if (idx < N_NODES) s += g_count[idx];
    }
    partial[t] = s;
    __syncthreads();

    for (int off = 1; off < SCAN_THREADS; off <<= 1) {
        int u = (t >= off) ? partial[t - off] : 0;
        __syncthreads();
        partial[t] += u;
        __syncthreads();
    }

    int run = partial[t] - s;
    for (int i = 0; i < CHUNK; i++) {
        int idx = base + i;
        if (idx < N_NODES) {
            g_offset[idx] = run;
            g_cursor[idx] = run;
            run += g_count[idx];
        }
    }
    if (t == SCAN_THREADS - 1) g_offset[N_NODES] = partial[SCAN_THREADS - 1];
}

__global__ void scatter_kernel(const int* __restrict__ esrc,
                               const int* __restrict__ etgt) {
    int i = blockIdx.x * blockDim.x + threadIdx.x;
    if (i < N_EDGES) {
        int pos = atomicAdd(&g_cursor[etgt[i]], 1);
        g_src_sorted[pos] = esrc[i];
    }
}

// ---------------- Kernel 2: gather, TWO independent nodes per warp -----------
// Each warp owns nodes 2w and 2w+1 and interleaves their 4-edge groups: node
// A's k-row loads are in flight while node B's math executes and vice versa
// (8 outstanding row loads per warp vs 4). All branch predicates are
// warp-uniform (CSR offsets), so no divergence. Src indices come from
// warp-uniform scalar __ldg (broadcast) instead of the 32-wide shfl dance.
__global__ void __launch_bounds__(256)
gather2_kernel(const float* __restrict__ attn, float* __restrict__ out) {
    __shared__ float a_s[128];
    if (threadIdx.x < 128) a_s[threadIdx.x] = attn[threadIdx.x];
    __syncthreads();

    const int w = (blockIdx.x * blockDim.x + threadIdx.x) >> 5;
    const int nA = w * 2;
    if (nA >= N_NODES) return;
    const int nB = nA + 1;
    const bool hasB = (nB < N_NODES);
    const int lane = threadIdx.x & 31;
    const int part = lane & 3;
    const int h = lane >> 2;

    const float a0 = a_s[(part * 4 + 0) * 8 + h];
    const float a1 = a_s[(part * 4 + 1) * 8 + h];
    const float a2 = a_s[(part * 4 + 2) * 8 + h];
    const float a3 = a_s[(part * 4 + 3) * 8 + h];

    const float4 qvA = *(const float4*)(g_q + (size_t)nA * 128 + lane * 4);
    float4 qvB = make_float4(0.f, 0.f, 0.f, 0.f);
    const int sA = g_offset[nA];
    const int eA = g_offset[nA + 1];
    int eB = 0, bB = 0;
    if (hasB) {
        qvB = *(const float4*)(g_q + (size_t)nB * 128 + lane * 4);
        bB = eA;                 // CSR is contiguous: sB == eA
        eB = g_offset[nB + 1];
    }

    float4 accA = make_float4(0.f, 0.f, 0.f, 0.f);
    float4 accB = make_float4(0.f, 0.f, 0.f, 0.f);
    float dA = 0.f, dB = 0.f;
    int bA = sA;

    while (bA < eA || bB < eB) {
        const int cA = eA - bA;      // >0 means node A still active
        const int cB = eB - bB;
        float4 kA0, kA1, kA2, kA3, kB0, kB1, kB2, kB3;

        // issue ALL loads first (up to 8 rows in flight)
        if (cA > 0) {
            const int last = eA - 1;
            const int sa0 = __ldg(g_src_sorted + bA);
            const int sa1 = __ldg(g_src_sorted + min(bA + 1, last));
            const int sa2 = __ldg(g_src_sorted + min(bA + 2, last));
            const int sa3 = __ldg(g_src_sorted + min(bA + 3, last));
            kA0 = *(const float4*)(g_k + (size_t)sa0 * 128 + lane * 4);
            kA1 = *(const float4*)(g_k + (size_t)sa1 * 128 + lane * 4);
            kA2 = *(const float4*)(g_k + (size_t)sa2 * 128 + lane * 4);
            kA3 = *(const float4*)(g_k + (size_t)sa3 * 128 + lane * 4);
        }
        if (cB > 0) {
            const int last = eB - 1;
            const int sb0 = __ldg(g_src_sorted + bB);
            const int sb1 = __ldg(g_src_sorted + min(bB + 1, last));
            const int sb2 = __ldg(g_src_sorted + min(bB + 2, last));
            const int sb3 = __ldg(g_src_sorted + min(bB + 3, last));
            kB0 = *(const float4*)(g_k + (size_t)sb0 * 128 + lane * 4);
            kB1 = *(const float4*)(g_k + (size_t)sb1 * 128 + lane * 4);
            kB2 = *(const float4*)(g_k + (size_t)sb2 * 128 + lane * 4);
            kB3 = *(const float4*)(g_k + (size_t)sb3 * 128 + lane * 4);
        }

        if (cA > 0) {
            float p0 = lrelu(qvA.x + kA0.x) * a0 + lrelu(qvA.y + kA0.y) * a1 +
                       lrelu(qvA.z + kA0.z) * a2 + lrelu(qvA.w + kA0.w) * a3;
            float p1 = lrelu(qvA.x + kA1.x) * a0 + lrelu(qvA.y + kA1.y) * a1 +
                       lrelu(qvA.z + kA1.z) * a2 + lrelu(qvA.w + kA1.w) * a3;
            float p2 = lrelu(qvA.x + kA2.x) * a0 + lrelu(qvA.y + kA2.y) * a1 +
                       lrelu(qvA.z + kA2.z) * a2 + lrelu(qvA.w + kA2.w) * a3;
            float p3 = lrelu(qvA.x + kA3.x) * a0 + lrelu(qvA.y + kA3.y) * a1 +
                       lrelu(qvA.z + kA3.z) * a2 + lrelu(qvA.w + kA3.w) * a3;
            p0 += __shfl_xor_sync(0xffffffffu, p0, 1);
            p1 += __shfl_xor_sync(0xffffffffu, p1, 1);
            p2 += __shfl_xor_sync(0xffffffffu, p2, 1);
            p3 += __shfl_xor_sync(0xffffffffu, p3, 1);
            p0 += __shfl_xor_sync(0xffffffffu, p0, 2);
            p1 += __shfl_xor_sync(0xffffffffu, p1, 2);
            p2 += __shfl_xor_sync(0xffffffffu, p2, 2);
            p3 += __shfl_xor_sync(0xffffffffu, p3, 2);
            const float u0 = __expf(p0);
            const float u1 = (1 < cA) ? __expf(p1) : 0.f;
            const float u2 = (2 < cA) ? __expf(p2) : 0.f;
            const float u3 = (3 < cA) ? __expf(p3) : 0.f;
            accA.x += u0 * kA0.x + u1 * kA1.x + u2 * kA2.x + u3 * kA3.x;
            accA.y += u0 * kA0.y + u1 * kA1.y + u2 * kA2.y + u3 * kA3.y;
            accA.z += u0 * kA0.z + u1 * kA1.z + u2 * kA2.z + u3 * kA3.z;
            accA.w += u0 * kA0.w + u1 * kA1.w + u2 * kA2.w + u3 * kA3.w;
            dA += (u0 + u1) + (u2 + u3);
        }
        if (cB > 0) {
            float p0 = lrelu(qvB.x + kB0.x) * a0 + lrelu(qvB.y + kB0.y) * a1 +
                       lrelu(qvB.z + kB0.z) * a2 + lrelu(qvB.w + kB0.w) * a3;
            float p1 = lrelu(qvB.x + kB1.x) * a0 + lrelu(qvB.y + kB1.y) * a1 +
                       lrelu(qvB.z + kB1.z) * a2 + lrelu(qvB.w + kB1.w) * a3;
            float p2 = lrelu(qvB.x + kB2.x) * a0 + lrelu(qvB.y + kB2.y) * a1 +
                       lrelu(qvB.z + kB2.z) * a2 + lrelu(qvB.w + kB2.w) * a3;
            float p3 = lrelu(qvB.x + kB3.x) * a0 + lrelu(qvB.y + kB3.y) * a1 +
                       lrelu(qvB.z + kB3.z) * a2 + lrelu(qvB.w + kB3.w) * a3;
            p0 += __shfl_xor_sync(0xffffffffu, p0, 1);
            p1 += __shfl_xor_sync(0xffffffffu, p1, 1);
            p2 += __shfl_xor_sync(0xffffffffu, p2, 1);
            p3 += __shfl_xor_sync(0xffffffffu, p3, 1);
            p0 += __shfl_xor_sync(0xffffffffu, p0, 2);
            p1 += __shfl_xor_sync(0xffffffffu, p1, 2);
            p2 += __shfl_xor_sync(0xffffffffu, p2, 2);
            p3 += __shfl_xor_sync(0xffffffffu, p3, 2);
            const float u0 = __expf(p0);
            const float u1 = (1 < cB) ? __expf(p1) : 0.f;
            const float u2 = (2 < cB) ? __expf(p2) : 0.f;
            const float u3 = (3 < cB) ? __expf(p3) : 0.f;
            accB.x += u0 * kB0.x + u1 * kB1.x + u2 * kB2.x + u3 * kB3.x;
            accB.y += u0 * kB0.y + u1 * kB1.y + u2 * kB2.y + u3 * kB3.y;
            accB.z += u0 * kB0.z + u1 * kB1.z + u2 * kB2.z + u3 * kB3.z;
            accB.w += u0 * kB0.w + u1 * kB1.w + u2 * kB2.w + u3 * kB3.w;
            dB += (u0 + u1) + (u2 + u3);
        }
        bA += 4;
        bB += 4;
    }

    {
        const float inv = (dA > 0.f) ? 1.f / dA : 0.f;
        float4 o;
        o.x = fmaxf(accA.x * inv, 0.f);
        o.y = fmaxf(accA.y * inv, 0.f);
        o.z = fmaxf(accA.z * inv, 0.f);
        o.w = fmaxf(accA.w * inv, 0.f);
        *(float4*)(out + (size_t)nA * 128 + lane * 4) = o;
    }
    if (hasB) {
        const float inv = (dB > 0.f) ? 1.f / dB : 0.f;
        float4 o;
        o.x = fmaxf(accB.x * inv, 0.f);
        o.y = fmaxf(accB.y * inv, 0.f);
        o.z = fmaxf(accB.z * inv, 0.f);
        o.w = fmaxf(accB.w * inv, 0.f);
        *(float4*)(out + (size_t)nB * 128 + lane * 4) = o;
    }
}

// ---------------- launch (serial) --------------------------------------------
extern "C" void kernel_launch(void* const* d_in, const int* in_sizes, int n_in,
                              void* d_out, int out_size) {
    const float* x    = (const float*)d_in[0];
    const float* wq   = (const float*)d_in[1];
    const float* bq   = (const float*)d_in[2];
    const float* wk   = (const float*)d_in[3];
    const float* bk   = (const float*)d_in[4];
    const float* attn = (const float*)d_in[5];
    const int*   esrc = (const int*)d_in[6];
    const int*   etgt = (const int*)d_in[7];
    float* out = (float*)d_out;

    // tensor-core Q/K GEMM first: ~101.5KB smem, 2 CTAs/SM (R13 config)
    static const size_t gemm_smem =
        (128 * WS_STRIDE + GEMM_TILE_N * XS_STRIDE) * 4 + 128 * 4;
    cudaFuncSetAttribute(qk_gemm_tc_kernel,
                         cudaFuncAttributeMaxDynamicSharedMemorySize,
                         (int)gemm_smem);
    dim3 gemm_grid(148, 2);
    qk_gemm_tc_kernel<<<gemm_grid, GEMM_BLOCK, gemm_smem>>>(x, wq, bq, wk, bk);

    // CSR build (zero histogram via symbol address query, no alloc)
    void* count_ptr = nullptr;
    cudaGetSymbolAddress(&count_ptr, g_count);
    cudaMemsetAsync(count_ptr, 0, N_NODES * sizeof(int), 0);
    hist_kernel<<<(N_EDGES + 255) / 256, 256>>>(etgt);
    scan_kernel<<<1, SCAN_THREADS>>>();
    scatter_kernel<<<(N_EDGES + 255) / 256, 256>>>(esrc, etgt);

    // gather: 2 nodes per warp, 8 warps per 256-thread block
    const int n_warps = (N_NODES + 1) / 2;
    gather2_kernel<<<(n_warps * 32 + 255) / 256, 256>>>(attn, out);
}